// round 5
// baseline (speedup 1.0000x reference)
#include <cuda_runtime.h>
#include <math.h>
#include <stdint.h>

#define HD   512
#define BD   32
#define SD   2048
#define K2   1024
#define W4H  2048
#define NEGV (-1e10f)

#define AMAX   6.5f
#define WMAX   0.0221f
#define QMAX   32512.0f

#define TPB    256
#define CHK    128        /* k elements (bytes) per chunk */
#define NCH    8

#define OFF_A1 0
#define OFF_A2 16384
#define OFF_B1 32768
#define OFF_B2 49152
#define BUFSZ  65536
#define SMEM_TOTAL (2 * BUFSZ)

__device__ float g_hb[BD * HD];
__device__ float g_attnp[4 * BD * SD];
__device__ __align__(16) uint8_t g_a1[(size_t)SD * BD * K2];
__device__ __align__(16) uint8_t g_a2[(size_t)SD * BD * K2];
__device__ __align__(16) uint8_t g_w1[HD * K2];
__device__ __align__(16) uint8_t g_w2[HD * K2];

// ---------------------------------------------------------------- helpers
__device__ __forceinline__ uint32_t smem_u32(const void* p) {
    uint32_t a;
    asm("{ .reg .u64 t; cvta.to.shared.u64 t, %1; cvt.u32.u64 %0, t; }"
        : "=r"(a) : "l"(p));
    return a;
}
__device__ __forceinline__ void cp16(uint32_t dst, const void* src) {
    asm volatile("cp.async.cg.shared.global [%0], [%1], 16;"
                 :: "r"(dst), "l"(src) : "memory");
}
__device__ __forceinline__ void ldmx4(uint32_t* r, uint32_t addr) {
    asm volatile("ldmatrix.sync.aligned.m8n8.x4.shared.b16 {%0,%1,%2,%3}, [%4];"
                 : "=r"(r[0]), "=r"(r[1]), "=r"(r[2]), "=r"(r[3]) : "r"(addr));
}
__device__ __forceinline__ void imma_ss(int* c, const uint32_t* a, uint32_t b0, uint32_t b1) {
    asm("mma.sync.aligned.m16n8k32.row.col.s32.s8.s8.s32 "
        "{%0,%1,%2,%3}, {%4,%5,%6,%7}, {%8,%9}, {%0,%1,%2,%3};"
        : "+r"(c[0]), "+r"(c[1]), "+r"(c[2]), "+r"(c[3])
        : "r"(a[0]), "r"(a[1]), "r"(a[2]), "r"(a[3]), "r"(b0), "r"(b1));
}

// quantize 4 fp32 -> centered signed limbs: q = 256*h + l, h,l in s8
__device__ __forceinline__ void quant4(float4 xv, float scale, float cl,
                                       uint32_t& p1, uint32_t& p2) {
    int q0 = __float2int_rn(fminf(fmaxf(xv.x, -cl), cl) * scale);
    int q1 = __float2int_rn(fminf(fmaxf(xv.y, -cl), cl) * scale);
    int q2 = __float2int_rn(fminf(fmaxf(xv.z, -cl), cl) * scale);
    int q3 = __float2int_rn(fminf(fmaxf(xv.w, -cl), cl) * scale);
    int h0 = (q0 + 128) >> 8, l0 = q0 - (h0 << 8);
    int h1 = (q1 + 128) >> 8, l1 = q1 - (h1 << 8);
    int h2 = (q2 + 128) >> 8, l2 = q2 - (h2 << 8);
    int h3 = (q3 + 128) >> 8, l3 = q3 - (h3 << 8);
    p1 = ((uint32_t)(h0 & 0xFF))       | ((uint32_t)(h1 & 0xFF) << 8)
       | ((uint32_t)(h2 & 0xFF) << 16) | ((uint32_t)(h3 & 0xFF) << 24);
    p2 = ((uint32_t)(l0 & 0xFF))       | ((uint32_t)(l1 & 0xFF) << 8)
       | ((uint32_t)(l2 & 0xFF) << 16) | ((uint32_t)(l3 & 0xFF) << 24);
}

// FMA-pipe-only tanh (no MUFU). |err| <= ~2.3e-5.
__device__ __forceinline__ float tanh_fast(float x) {
    float xa = fminf(fmaxf(x, -5.7f), 5.7f);
    float z  = xa * 2.885390081777927f;
    float fz = z + 12582912.0f;
    int   ni = __float_as_int(fz);
    float f  = z - (fz - 12582912.0f);
    float p  = 1.3333558146e-3f;
    p = fmaf(p, f, 9.6181291076e-3f);
    p = fmaf(p, f, 5.5504108664e-2f);
    p = fmaf(p, f, 2.4022650696e-1f);
    p = fmaf(p, f, 6.9314718056e-1f);
    p = fmaf(p, f, 1.0f);
    float s = __int_as_float((ni << 23) + 0x3F800000);
    float t = p * s;
    float d = t + 1.0f;
    float r = __int_as_float(0x7EF311C3 - __float_as_int(d));
    r = r * (2.0f - d * r);
    r = r * (2.0f - d * r);
    r = r * (2.0f - d * r);
    return (t - 1.0f) * r;
}

// ---------------- prep A: quantize eo into 2 centered limb arrays
__global__ void prep_a_kernel(const float* __restrict__ eo) {
    size_t base = ((size_t)blockIdx.x * 256 + threadIdx.x) * 16;
    const float scale = QMAX / AMAX;
    uint32_t h[4], l[4];
    #pragma unroll
    for (int i = 0; i < 4; i++) {
        float4 xv = *(const float4*)(eo + base + i * 4);
        quant4(xv, scale, AMAX, h[i], l[i]);
    }
    *(uint4*)(g_a1 + base) = make_uint4(h[0], h[1], h[2], h[3]);
    *(uint4*)(g_a2 + base) = make_uint4(l[0], l[1], l[2], l[3]);
}

// ---------------- prep W: quantize attn_w[:, 1024:2048]
__global__ void prep_w_kernel(const float* __restrict__ attn_w) {
    int n = blockIdx.x;
    int k = threadIdx.x * 4;
    float4 wv = *(const float4*)(attn_w + (size_t)n * W4H + 1024 + k);
    uint32_t h, l;
    quant4(wv, QMAX / WMAX, WMAX, h, l);
    *(uint32_t*)(g_w1 + (size_t)n * K2 + k) = h;
    *(uint32_t*)(g_w2 + (size_t)n * K2 + k) = l;
}

// ---------------- hb: g_hb[b][h] = bias[h] + hidden[b,:] . W[h, :1024]
__global__ void hb_kernel(const float* __restrict__ hidden,
                          const float* __restrict__ attn_w,
                          const float* __restrict__ attn_b) {
    int hc = blockIdx.x, b = blockIdx.y;
    __shared__ float sh[K2];
    for (int i = threadIdx.x; i < K2; i += 256) sh[i] = hidden[b * K2 + i];
    __syncthreads();
    int w = threadIdx.x >> 5, lane = threadIdx.x & 31;
    #pragma unroll
    for (int hi = 0; hi < 8; hi++) {
        int h = hc * 64 + w * 8 + hi;
        const float* wr = attn_w + (size_t)h * W4H;
        float s = 0.f;
        for (int k = lane * 4; k < K2; k += 128) {
            float4 wv = *(const float4*)(wr + k);
            s += sh[k] * wv.x + sh[k + 1] * wv.y + sh[k + 2] * wv.z + sh[k + 3] * wv.w;
        }
        #pragma unroll
        for (int o = 16; o > 0; o >>= 1) s += __shfl_down_sync(0xffffffffu, s, o);
        if (lane == 0) g_hb[b * HD + h] = s + attn_b[h];
    }
}

// ---------------- energy: int8 IMMA 2-limb GEMM + fused tanh.v epilogue
__global__ void __launch_bounds__(TPB, 1)
energy_kernel(const float* __restrict__ v) {
    extern __shared__ char smem[];
    const uint32_t sb = smem_u32(smem);
    const int tid  = threadIdx.x;
    const int lane = tid & 31;
    const int warp = tid >> 5;
    const int wm   = warp >> 2;          // 0..1
    const int wn   = warp & 3;           // 0..3

    const int m0 = blockIdx.x * 128;
    const int nsl = blockIdx.y;
    const int n0 = nsl * 128;

    int accm[4][4][4], accx[4][4][4];
    #pragma unroll
    for (int mf = 0; mf < 4; mf++)
        #pragma unroll
        for (int nf = 0; nf < 4; nf++)
            #pragma unroll
            for (int i = 0; i < 4; i++) { accm[mf][nf][i] = 0; accx[mf][nf][i] = 0; }

    const int a_rg = (lane & 7) + ((lane >> 3) & 1) * 8;
    const int a_u  = lane >> 4;
    const int b_rg = (lane & 7) + ((lane >> 4) << 3);
    const int b_u  = (lane >> 3) & 1;

    auto issue = [&](int kc, int buf) {
        const uint32_t bs = sb + buf * BUFSZ;
        #pragma unroll
        for (int j = 0; j < 4; j++) {
            int x = tid + j * 256;       // 0..1023
            int r = x >> 3, u = x & 7;
            uint32_t d = (uint32_t)(r * 128 + ((u ^ (r & 7)) << 4));
            size_t ao = (size_t)(m0 + r) * K2 + kc + u * 16;
            size_t bo = (size_t)(n0 + r) * K2 + kc + u * 16;
            cp16(bs + OFF_A1 + d, g_a1 + ao);
            cp16(bs + OFF_A2 + d, g_a2 + ao);
            cp16(bs + OFF_B1 + d, g_w1 + bo);
            cp16(bs + OFF_B2 + d, g_w2 + bo);
        }
        asm volatile("cp.async.commit_group;" ::: "memory");
    };

    issue(0, 0);
    issue(CHK, 1);

    for (int c = 0; c < NCH; c++) {
        if (c < NCH - 1) asm volatile("cp.async.wait_group 1;" ::: "memory");
        else             asm volatile("cp.async.wait_group 0;" ::: "memory");
        __syncthreads();

        const uint32_t bs = sb + (c & 1) * BUFSZ;
        #pragma unroll
        for (int ks = 0; ks < 4; ks++) {
            uint32_t a1[4][4], a2[4][4];
            #pragma unroll
            for (int mf = 0; mf < 4; mf++) {
                int row = wm * 64 + mf * 16 + a_rg;
                int u   = ks * 2 + a_u;
                uint32_t ad = (uint32_t)(row * 128 + ((u ^ (row & 7)) << 4));
                ldmx4(a1[mf], bs + OFF_A1 + ad);
                ldmx4(a2[mf], bs + OFF_A2 + ad);
            }
            #pragma unroll
            for (int g = 0; g < 2; g++) {
                uint32_t b1[4], b2[4];
                int row = wn * 32 + g * 16 + b_rg;
                int u   = ks * 2 + b_u;
                uint32_t bd = (uint32_t)(row * 128 + ((u ^ (row & 7)) << 4));
                ldmx4(b1, bs + OFF_B1 + bd);
                ldmx4(b2, bs + OFF_B2 + bd);
                #pragma unroll
                for (int mf = 0; mf < 4; mf++) {
                    #pragma unroll
                    for (int t = 0; t < 2; t++) {
                        int nf = g * 2 + t;
                        imma_ss(accm[mf][nf], a1[mf], b1[t * 2], b1[t * 2 + 1]);
                        imma_ss(accx[mf][nf], a1[mf], b2[t * 2], b2[t * 2 + 1]);
                        imma_ss(accx[mf][nf], a2[mf], b1[t * 2], b1[t * 2 + 1]);
                    }
                }
            }
        }
        __syncthreads();
        if (c + 2 < NCH) issue((c + 2) * CHK, c & 1);
    }

    // -------- epilogue
    float* hb_t = (float*)smem;                    // [128][33]
    float* v_s  = (float*)(smem + 16896);          // [128]
    float* red  = (float*)(smem + 17408);          // [128][4]
    for (int i = tid; i < 128 * BD; i += TPB) {
        int n = i >> 5, b = i & 31;
        hb_t[n * 33 + b] = g_hb[b * HD + n0 + n];
    }
    if (tid < 128) v_s[tid] = v[n0 + tid];
    __syncthreads();

    const float c1 = (AMAX / QMAX) * (WMAX / QMAX) * 65536.0f;
    const float c2 = (AMAX / QMAX) * (WMAX / QMAX) * 256.0f;
    const int quad = lane >> 2, qlane = lane & 3;
    #pragma unroll
    for (int mf = 0; mf < 4; mf++) {
        #pragma unroll
        for (int h = 0; h < 2; h++) {
            int rl = wm * 64 + mf * 16 + h * 8 + quad;
            int b  = (m0 + rl) & 31;
            float p = 0.f;
            #pragma unroll
            for (int nf = 0; nf < 4; nf++) {
                int cl = wn * 32 + nf * 8 + qlane * 2;
                float e0 = fmaf(c1, (float)accm[mf][nf][h * 2],
                           fmaf(c2, (float)accx[mf][nf][h * 2], hb_t[cl * 33 + b]));
                float e1 = fmaf(c1, (float)accm[mf][nf][h * 2 + 1],
                           fmaf(c2, (float)accx[mf][nf][h * 2 + 1], hb_t[(cl + 1) * 33 + b]));
                p = fmaf(tanh_fast(e0), v_s[cl],     p);
                p = fmaf(tanh_fast(e1), v_s[cl + 1], p);
            }
            p += __shfl_xor_sync(0xffffffffu, p, 1);
            p += __shfl_xor_sync(0xffffffffu, p, 2);
            if (qlane == 0) red[rl * 4 + wn] = p;
        }
    }
    __syncthreads();
    if (tid < 128) {
        int m = m0 + tid;
        float lg = red[tid * 4] + red[tid * 4 + 1] + red[tid * 4 + 2] + red[tid * 4 + 3];
        g_attnp[nsl * BD * SD + (m & 31) * SD + (m >> 5)] = lg;
    }
}

// ---------------- softmax over S per batch row (sums 4 N-slice partials)
__global__ void softmax_kernel(const int* __restrict__ mask, float* __restrict__ out) {
    int b = blockIdx.x;
    int tid = threadIdx.x;             // 256
    int warp = tid >> 5, lane = tid & 31;
    __shared__ float sred[8];

    float vals[8];
    float mx = -INFINITY;
    #pragma unroll
    for (int i = 0; i < 8; i++) {
        int s = tid + i * 256;
        float raw = g_attnp[b * SD + s]
                  + g_attnp[BD * SD + b * SD + s]
                  + g_attnp[2 * BD * SD + b * SD + s]
                  + g_attnp[3 * BD * SD + b * SD + s];
        vals[i] = mask[b * SD + s] ? raw : NEGV;
        mx = fmaxf(mx, vals[i]);
    }
    #pragma unroll
    for (int o = 16; o > 0; o >>= 1) mx = fmaxf(mx, __shfl_xor_sync(0xffffffffu, mx, o));
    if (lane == 0) sred[warp] = mx;
    __syncthreads();
    float bm = sred[0];
    #pragma unroll
    for (int w = 1; w < 8; w++) bm = fmaxf(bm, sred[w]);

    float sum = 0.f;
    #pragma unroll
    for (int i = 0; i < 8; i++) {
        vals[i] = expf(vals[i] - bm);
        sum += vals[i];
    }
    #pragma unroll
    for (int o = 16; o > 0; o >>= 1) sum += __shfl_xor_sync(0xffffffffu, sum, o);
    __syncthreads();
    if (lane == 0) sred[warp] = sum;
    __syncthreads();
    float bs = 0.f;
    #pragma unroll
    for (int w = 0; w < 8; w++) bs += sred[w];
    float inv = 1.f / bs;
    #pragma unroll
    for (int i = 0; i < 8; i++) out[b * SD + tid + i * 256] = vals[i] * inv;
}

extern "C" void kernel_launch(void* const* d_in, const int* in_sizes, int n_in,
                              void* d_out, int out_size) {
    const float* hidden = (const float*)d_in[0];
    const float* eo     = (const float*)d_in[1];
    const int*   mask   = (const int*)  d_in[2];
    const float* attn_w = (const float*)d_in[3];
    const float* attn_b = (const float*)d_in[4];
    const float* v      = (const float*)d_in[5];
    float* out = (float*)d_out;

    cudaFuncSetAttribute(energy_kernel,
                         cudaFuncAttributeMaxDynamicSharedMemorySize, SMEM_TOTAL);

    prep_a_kernel<<<(SD * BD * K2) / (256 * 16), 256>>>(eo);
    prep_w_kernel<<<HD, 256>>>(attn_w);
    hb_kernel<<<dim3(8, BD), 256>>>(hidden, attn_w, attn_b);
    energy_kernel<<<dim3(SD * BD / 128, 4), TPB, SMEM_TOTAL>>>(v);
    softmax_kernel<<<BD, 256>>>(mask, out);
}

// round 6
// speedup vs baseline: 5.0640x; 5.0640x over previous
#include <cuda_runtime.h>
#include <cuda_fp16.h>
#include <math.h>
#include <stdint.h>

#define HD   512
#define BD   32
#define SD   2048
#define K2   1024
#define W4H  2048
#define NEGV (-1e10f)

#define TPB  256
#define NCH  16            /* k chunks of 64 */

#define OFF_A 0            /* 128 rows * 128B = 16KB */
#define OFF_B 16384        /* 256 rows * 128B = 32KB */
#define BUFSZ 49152
#define SMEM_TOTAL (2 * BUFSZ)

__device__ float g_hb[BD * HD];
__device__ float g_attnp[2 * BD * SD];
__device__ __align__(16) __half g_ah[(size_t)SD * BD * K2];
__device__ __align__(16) __half g_wh[HD * K2];

// ---------------------------------------------------------------- helpers
__device__ __forceinline__ uint32_t smem_u32(const void* p) {
    uint32_t a;
    asm("{ .reg .u64 t; cvta.to.shared.u64 t, %1; cvt.u32.u64 %0, t; }"
        : "=r"(a) : "l"(p));
    return a;
}
__device__ __forceinline__ void cp16(uint32_t dst, const void* src) {
    asm volatile("cp.async.cg.shared.global [%0], [%1], 16;"
                 :: "r"(dst), "l"(src) : "memory");
}
__device__ __forceinline__ void ldmx4(uint32_t* r, uint32_t addr) {
    asm volatile("ldmatrix.sync.aligned.m8n8.x4.shared.b16 {%0,%1,%2,%3}, [%4];"
                 : "=r"(r[0]), "=r"(r[1]), "=r"(r[2]), "=r"(r[3]) : "r"(addr));
}
__device__ __forceinline__ void hmma(float* c, const uint32_t* a,
                                     uint32_t b0, uint32_t b1) {
    asm("mma.sync.aligned.m16n8k16.row.col.f32.f16.f16.f32 "
        "{%0,%1,%2,%3}, {%4,%5,%6,%7}, {%8,%9}, {%0,%1,%2,%3};"
        : "+f"(c[0]), "+f"(c[1]), "+f"(c[2]), "+f"(c[3])
        : "r"(a[0]), "r"(a[1]), "r"(a[2]), "r"(a[3]), "r"(b0), "r"(b1));
}

// FMA-pipe-only tanh (no MUFU). |err| <= ~2.3e-5.
__device__ __forceinline__ float tanh_fast(float x) {
    float xa = fminf(fmaxf(x, -5.7f), 5.7f);
    float z  = xa * 2.885390081777927f;
    float fz = z + 12582912.0f;
    int   ni = __float_as_int(fz);
    float f  = z - (fz - 12582912.0f);
    float p  = 1.3333558146e-3f;
    p = fmaf(p, f, 9.6181291076e-3f);
    p = fmaf(p, f, 5.5504108664e-2f);
    p = fmaf(p, f, 2.4022650696e-1f);
    p = fmaf(p, f, 6.9314718056e-1f);
    p = fmaf(p, f, 1.0f);
    float s = __int_as_float((ni << 23) + 0x3F800000);
    float t = p * s;
    float d = t + 1.0f;
    float r = __int_as_float(0x7EF311C3 - __float_as_int(d));
    r = r * (2.0f - d * r);
    r = r * (2.0f - d * r);
    r = r * (2.0f - d * r);
    return (t - 1.0f) * r;
}

// ---------------- prep A: eo fp32 -> fp16
__global__ void prep_a_kernel(const float* __restrict__ eo) {
    size_t base = ((size_t)blockIdx.x * 256 + threadIdx.x) * 16;
    uint32_t o[8];
    #pragma unroll
    for (int i = 0; i < 4; i++) {
        float4 x = *(const float4*)(eo + base + i * 4);
        __half2 h01 = __floats2half2_rn(x.x, x.y);
        __half2 h23 = __floats2half2_rn(x.z, x.w);
        o[i * 2]     = *(uint32_t*)&h01;
        o[i * 2 + 1] = *(uint32_t*)&h23;
    }
    *(uint4*)(g_ah + base)     = make_uint4(o[0], o[1], o[2], o[3]);
    *(uint4*)(g_ah + base + 8) = make_uint4(o[4], o[5], o[6], o[7]);
}

// ---------------- prep W: attn_w[:,1024:2048] * 64 -> fp16
__global__ void prep_w_kernel(const float* __restrict__ attn_w) {
    int n = blockIdx.x;
    int k = threadIdx.x * 4;
    float4 w = *(const float4*)(attn_w + (size_t)n * W4H + 1024 + k);
    __half2 h01 = __floats2half2_rn(w.x * 64.f, w.y * 64.f);
    __half2 h23 = __floats2half2_rn(w.z * 64.f, w.w * 64.f);
    *(uint2*)(g_wh + (size_t)n * K2 + k) =
        make_uint2(*(uint32_t*)&h01, *(uint32_t*)&h23);
}

// ---------------- hb: g_hb[b][h] = bias[h] + hidden[b,:] . W[h, :1024]
__global__ void hb_kernel(const float* __restrict__ hidden,
                          const float* __restrict__ attn_w,
                          const float* __restrict__ attn_b) {
    int hc = blockIdx.x, b = blockIdx.y;
    __shared__ float sh[K2];
    for (int i = threadIdx.x; i < K2; i += 256) sh[i] = hidden[b * K2 + i];
    __syncthreads();
    int w = threadIdx.x >> 5, lane = threadIdx.x & 31;
    #pragma unroll
    for (int hi = 0; hi < 8; hi++) {
        int h = hc * 64 + w * 8 + hi;
        const float* wr = attn_w + (size_t)h * W4H;
        float s = 0.f;
        for (int k = lane * 4; k < K2; k += 128) {
            float4 wv = *(const float4*)(wr + k);
            s += sh[k] * wv.x + sh[k + 1] * wv.y + sh[k + 2] * wv.z + sh[k + 3] * wv.w;
        }
        #pragma unroll
        for (int o = 16; o > 0; o >>= 1) s += __shfl_down_sync(0xffffffffu, s, o);
        if (lane == 0) g_hb[b * HD + h] = s + attn_b[h];
    }
}

// ---------------- energy: fp16 HMMA GEMM + fused tanh.v epilogue
__global__ void __launch_bounds__(TPB, 1)
energy_kernel(const float* __restrict__ v) {
    extern __shared__ char smem[];
    const uint32_t sb = smem_u32(smem);
    const int tid  = threadIdx.x;
    const int lane = tid & 31;
    const int warp = tid >> 5;
    const int wm   = warp >> 2;          // 0..1  (m64 half)
    const int wn   = warp & 3;           // 0..3  (n64 quarter)

    const int m0  = blockIdx.x * 128;
    const int nsl = blockIdx.y;
    const int n0  = nsl * 256;

    float acc[4][8][4];
    #pragma unroll
    for (int mf = 0; mf < 4; mf++)
        #pragma unroll
        for (int nf = 0; nf < 8; nf++)
            #pragma unroll
            for (int i = 0; i < 4; i++) acc[mf][nf][i] = 0.f;

    const int a_rg = (lane & 7) + ((lane >> 3) & 1) * 8;
    const int a_u  = lane >> 4;
    const int b_rg = (lane & 7) + ((lane >> 4) << 3);
    const int b_u  = (lane >> 3) & 1;

    auto issue = [&](int kc, int buf) {
        const uint32_t bs = sb + buf * BUFSZ;
        #pragma unroll
        for (int j = 0; j < 4; j++) {       // A: 128 rows x 8 units
            int x = tid + j * 256;          // 0..1023
            int r = x >> 3, u = x & 7;
            uint32_t d = (uint32_t)(r * 128 + ((u ^ (r & 7)) << 4));
            cp16(bs + OFF_A + d, g_ah + (size_t)(m0 + r) * K2 + kc + u * 8);
        }
        #pragma unroll
        for (int j = 0; j < 8; j++) {       // B: 256 rows x 8 units
            int x = tid + j * 256;          // 0..2047
            int r = x >> 3, u = x & 7;
            uint32_t d = (uint32_t)(r * 128 + ((u ^ (r & 7)) << 4));
            cp16(bs + OFF_B + d, g_wh + (size_t)(n0 + r) * K2 + kc + u * 8);
        }
        asm volatile("cp.async.commit_group;" ::: "memory");
    };

    issue(0, 0);
    issue(64, 1);

    for (int c = 0; c < NCH; c++) {
        if (c < NCH - 1) asm volatile("cp.async.wait_group 1;" ::: "memory");
        else             asm volatile("cp.async.wait_group 0;" ::: "memory");
        __syncthreads();

        const uint32_t bs = sb + (c & 1) * BUFSZ;
        #pragma unroll
        for (int ks = 0; ks < 4; ks++) {
            uint32_t af[4][4];
            #pragma unroll
            for (int mf = 0; mf < 4; mf++) {
                int row = wm * 64 + mf * 16 + a_rg;
                int u   = ks * 2 + a_u;
                ldmx4(af[mf], bs + OFF_A + (uint32_t)(row * 128 + ((u ^ (row & 7)) << 4)));
            }
            #pragma unroll
            for (int g = 0; g < 4; g++) {
                uint32_t bf[4];
                int row = wn * 64 + g * 16 + b_rg;
                int u   = ks * 2 + b_u;
                ldmx4(bf, bs + OFF_B + (uint32_t)(row * 128 + ((u ^ (row & 7)) << 4)));
                #pragma unroll
                for (int mf = 0; mf < 4; mf++) {
                    hmma(acc[mf][g * 2],     af[mf], bf[0], bf[1]);
                    hmma(acc[mf][g * 2 + 1], af[mf], bf[2], bf[3]);
                }
            }
        }
        __syncthreads();
        if (c + 2 < NCH) issue((c + 2) * 64, c & 1);
    }

    // -------- epilogue: tanh(E/64 + hb) . v
    float* hb_t = (float*)smem;                    // [256][33]
    float* v_s  = (float*)(smem + 33792);          // [256]
    float* red  = (float*)(smem + 34816);          // [128][4]
    for (int i = tid; i < 256 * BD; i += TPB) {
        int n = i >> 5, b = i & 31;
        hb_t[n * 33 + b] = g_hb[b * HD + n0 + n];
    }
    v_s[tid] = v[n0 + tid];
    __syncthreads();

    const float c1 = 1.0f / 64.0f;
    const int quad = lane >> 2, qlane = lane & 3;
    #pragma unroll
    for (int mf = 0; mf < 4; mf++) {
        #pragma unroll
        for (int h = 0; h < 2; h++) {
            int rl = wm * 64 + mf * 16 + h * 8 + quad;
            int b  = (m0 + rl) & 31;
            float p = 0.f;
            #pragma unroll
            for (int nf = 0; nf < 8; nf++) {
                int cl = wn * 64 + nf * 8 + qlane * 2;
                float e0 = fmaf(acc[mf][nf][h * 2],     c1, hb_t[cl * 33 + b]);
                float e1 = fmaf(acc[mf][nf][h * 2 + 1], c1, hb_t[(cl + 1) * 33 + b]);
                p = fmaf(tanh_fast(e0), v_s[cl],     p);
                p = fmaf(tanh_fast(e1), v_s[cl + 1], p);
            }
            p += __shfl_xor_sync(0xffffffffu, p, 1);
            p += __shfl_xor_sync(0xffffffffu, p, 2);
            if (qlane == 0) red[rl * 4 + wn] = p;
        }
    }
    __syncthreads();
    if (tid < 128) {
        int m = m0 + tid;
        float lg = red[tid * 4] + red[tid * 4 + 1] + red[tid * 4 + 2] + red[tid * 4 + 3];
        g_attnp[nsl * BD * SD + (m & 31) * SD + (m >> 5)] = lg;
    }
}

// ---------------- softmax over S per batch row (sums 2 N-slice partials)
__global__ void softmax_kernel(const int* __restrict__ mask, float* __restrict__ out) {
    int b = blockIdx.x;
    int tid = threadIdx.x;             // 256
    int warp = tid >> 5, lane = tid & 31;
    __shared__ float sred[8];

    float vals[8];
    float mx = -INFINITY;
    #pragma unroll
    for (int i = 0; i < 8; i++) {
        int s = tid + i * 256;
        float raw = g_attnp[b * SD + s] + g_attnp[BD * SD + b * SD + s];
        vals[i] = mask[b * SD + s] ? raw : NEGV;
        mx = fmaxf(mx, vals[i]);
    }
    #pragma unroll
    for (int o = 16; o > 0; o >>= 1) mx = fmaxf(mx, __shfl_xor_sync(0xffffffffu, mx, o));
    if (lane == 0) sred[warp] = mx;
    __syncthreads();
    float bm = sred[0];
    #pragma unroll
    for (int w = 1; w < 8; w++) bm = fmaxf(bm, sred[w]);

    float sum = 0.f;
    #pragma unroll
    for (int i = 0; i < 8; i++) {
        vals[i] = expf(vals[i] - bm);
        sum += vals[i];
    }
    #pragma unroll
    for (int o = 16; o > 0; o >>= 1) sum += __shfl_xor_sync(0xffffffffu, sum, o);
    __syncthreads();
    if (lane == 0) sred[warp] = sum;
    __syncthreads();
    float bs = 0.f;
    #pragma unroll
    for (int w = 0; w < 8; w++) bs += sred[w];
    float inv = 1.f / bs;
    #pragma unroll
    for (int i = 0; i < 8; i++) out[b * SD + tid + i * 256] = vals[i] * inv;
}

extern "C" void kernel_launch(void* const* d_in, const int* in_sizes, int n_in,
                              void* d_out, int out_size) {
    const float* hidden = (const float*)d_in[0];
    const float* eo     = (const float*)d_in[1];
    const int*   mask   = (const int*)  d_in[2];
    const float* attn_w = (const float*)d_in[3];
    const float* attn_b = (const float*)d_in[4];
    const float* v      = (const float*)d_in[5];
    float* out = (float*)d_out;

    cudaFuncSetAttribute(energy_kernel,
                         cudaFuncAttributeMaxDynamicSharedMemorySize, SMEM_TOTAL);

    prep_a_kernel<<<(SD * BD * K2) / (256 * 16), 256>>>(eo);
    prep_w_kernel<<<HD, 256>>>(attn_w);
    hb_kernel<<<dim3(8, BD), 256>>>(hidden, attn_w, attn_b);
    energy_kernel<<<dim3(SD * BD / 128, 2), TPB, SMEM_TOTAL>>>(v);
    softmax_kernel<<<BD, 256>>>(mask, out);
}

// round 7
// speedup vs baseline: 5.0976x; 1.0066x over previous
#include <cuda_runtime.h>
#include <cuda_fp16.h>
#include <math.h>
#include <stdint.h>

#define HD   512
#define BD   32
#define SD   2048
#define K2   1024
#define W4H  2048
#define NEGV (-1e10f)

#define TPB  512
#define NCH  16            /* k chunks of 64 */

#define OFF_A 0            /* 128 rows * 128B = 16KB */
#define OFF_B 16384        /* 256 rows * 128B = 32KB */
#define BUFSZ 49152
#define SMEM_TOTAL (2 * BUFSZ)

__device__ float g_hb[BD * HD];
__device__ float g_attnp[2 * BD * SD];
__device__ __align__(16) __half g_ah[(size_t)SD * BD * K2];
__device__ __align__(16) __half g_wh[HD * K2];

// ---------------------------------------------------------------- helpers
__device__ __forceinline__ uint32_t smem_u32(const void* p) {
    uint32_t a;
    asm("{ .reg .u64 t; cvta.to.shared.u64 t, %1; cvt.u32.u64 %0, t; }"
        : "=r"(a) : "l"(p));
    return a;
}
__device__ __forceinline__ void cp16(uint32_t dst, const void* src) {
    asm volatile("cp.async.cg.shared.global [%0], [%1], 16;"
                 :: "r"(dst), "l"(src) : "memory");
}
__device__ __forceinline__ void ldmx4(uint32_t* r, uint32_t addr) {
    asm volatile("ldmatrix.sync.aligned.m8n8.x4.shared.b16 {%0,%1,%2,%3}, [%4];"
                 : "=r"(r[0]), "=r"(r[1]), "=r"(r[2]), "=r"(r[3]) : "r"(addr));
}
__device__ __forceinline__ void hmma(float* c, const uint32_t* a,
                                     uint32_t b0, uint32_t b1) {
    asm("mma.sync.aligned.m16n8k16.row.col.f32.f16.f16.f32 "
        "{%0,%1,%2,%3}, {%4,%5,%6,%7}, {%8,%9}, {%0,%1,%2,%3};"
        : "+f"(c[0]), "+f"(c[1]), "+f"(c[2]), "+f"(c[3])
        : "r"(a[0]), "r"(a[1]), "r"(a[2]), "r"(a[3]), "r"(b0), "r"(b1));
}

// FMA-pipe-only tanh (no MUFU). |err| <= ~2.3e-5.
__device__ __forceinline__ float tanh_fast(float x) {
    float xa = fminf(fmaxf(x, -5.7f), 5.7f);
    float z  = xa * 2.885390081777927f;
    float fz = z + 12582912.0f;
    int   ni = __float_as_int(fz);
    float f  = z - (fz - 12582912.0f);
    float p  = 1.3333558146e-3f;
    p = fmaf(p, f, 9.6181291076e-3f);
    p = fmaf(p, f, 5.5504108664e-2f);
    p = fmaf(p, f, 2.4022650696e-1f);
    p = fmaf(p, f, 6.9314718056e-1f);
    p = fmaf(p, f, 1.0f);
    float s = __int_as_float((ni << 23) + 0x3F800000);
    float t = p * s;
    float d = t + 1.0f;
    float r = __int_as_float(0x7EF311C3 - __float_as_int(d));
    r = r * (2.0f - d * r);
    r = r * (2.0f - d * r);
    r = r * (2.0f - d * r);
    return (t - 1.0f) * r;
}

// ---------------- prep A: eo fp32 -> fp16
__global__ void prep_a_kernel(const float* __restrict__ eo) {
    size_t base = ((size_t)blockIdx.x * 256 + threadIdx.x) * 16;
    uint32_t o[8];
    #pragma unroll
    for (int i = 0; i < 4; i++) {
        float4 x = *(const float4*)(eo + base + i * 4);
        __half2 h01 = __floats2half2_rn(x.x, x.y);
        __half2 h23 = __floats2half2_rn(x.z, x.w);
        o[i * 2]     = *(uint32_t*)&h01;
        o[i * 2 + 1] = *(uint32_t*)&h23;
    }
    *(uint4*)(g_ah + base)     = make_uint4(o[0], o[1], o[2], o[3]);
    *(uint4*)(g_ah + base + 8) = make_uint4(o[4], o[5], o[6], o[7]);
}

// ---------------- prep W: attn_w[:,1024:2048] * 64 -> fp16
__global__ void prep_w_kernel(const float* __restrict__ attn_w) {
    int n = blockIdx.x;
    int k = threadIdx.x * 4;
    float4 w = *(const float4*)(attn_w + (size_t)n * W4H + 1024 + k);
    __half2 h01 = __floats2half2_rn(w.x * 64.f, w.y * 64.f);
    __half2 h23 = __floats2half2_rn(w.z * 64.f, w.w * 64.f);
    *(uint2*)(g_wh + (size_t)n * K2 + k) =
        make_uint2(*(uint32_t*)&h01, *(uint32_t*)&h23);
}

// ---------------- hb: g_hb[b][h] = bias[h] + hidden[b,:] . W[h, :1024]
__global__ void hb_kernel(const float* __restrict__ hidden,
                          const float* __restrict__ attn_w,
                          const float* __restrict__ attn_b) {
    int hc = blockIdx.x, b = blockIdx.y;
    __shared__ float sh[K2];
    for (int i = threadIdx.x; i < K2; i += 256) sh[i] = hidden[b * K2 + i];
    __syncthreads();
    int w = threadIdx.x >> 5, lane = threadIdx.x & 31;
    #pragma unroll
    for (int hi = 0; hi < 8; hi++) {
        int h = hc * 64 + w * 8 + hi;
        const float* wr = attn_w + (size_t)h * W4H;
        float s = 0.f;
        for (int k = lane * 4; k < K2; k += 128) {
            float4 wv = *(const float4*)(wr + k);
            s += sh[k] * wv.x + sh[k + 1] * wv.y + sh[k + 2] * wv.z + sh[k + 3] * wv.w;
        }
        #pragma unroll
        for (int o = 16; o > 0; o >>= 1) s += __shfl_down_sync(0xffffffffu, s, o);
        if (lane == 0) g_hb[b * HD + h] = s + attn_b[h];
    }
}

// ---------------- energy: fp16 HMMA GEMM, 16 warps, warp tile 32x64
__global__ void __launch_bounds__(TPB, 1)
energy_kernel(const float* __restrict__ v) {
    extern __shared__ char smem[];
    const uint32_t sb = smem_u32(smem);
    const int tid  = threadIdx.x;
    const int lane = tid & 31;
    const int warp = tid >> 5;
    const int wm   = warp >> 2;          // 0..3  (m32 quarter)
    const int wn   = warp & 3;           // 0..3  (n64 quarter)

    const int m0  = blockIdx.x * 128;
    const int nsl = blockIdx.y;
    const int n0  = nsl * 256;

    float acc[2][8][4];
    #pragma unroll
    for (int mf = 0; mf < 2; mf++)
        #pragma unroll
        for (int nf = 0; nf < 8; nf++)
            #pragma unroll
            for (int i = 0; i < 4; i++) acc[mf][nf][i] = 0.f;

    const int a_rg = (lane & 7) + ((lane >> 3) & 1) * 8;
    const int a_u  = lane >> 4;
    const int b_rg = (lane & 7) + ((lane >> 4) << 3);
    const int b_u  = (lane >> 3) & 1;

    auto issue = [&](int kc, int buf) {
        const uint32_t bs = sb + buf * BUFSZ;
        #pragma unroll
        for (int j = 0; j < 2; j++) {       // A: 128 rows x 8 units = 1024
            int x = tid + j * TPB;
            int r = x >> 3, u = x & 7;
            uint32_t d = (uint32_t)(r * 128 + ((u ^ (r & 7)) << 4));
            cp16(bs + OFF_A + d, g_ah + (size_t)(m0 + r) * K2 + kc + u * 8);
        }
        #pragma unroll
        for (int j = 0; j < 4; j++) {       // B: 256 rows x 8 units = 2048
            int x = tid + j * TPB;
            int r = x >> 3, u = x & 7;
            uint32_t d = (uint32_t)(r * 128 + ((u ^ (r & 7)) << 4));
            cp16(bs + OFF_B + d, g_wh + (size_t)(n0 + r) * K2 + kc + u * 8);
        }
        asm volatile("cp.async.commit_group;" ::: "memory");
    };

    issue(0, 0);
    issue(64, 1);

    for (int c = 0; c < NCH; c++) {
        if (c < NCH - 1) asm volatile("cp.async.wait_group 1;" ::: "memory");
        else             asm volatile("cp.async.wait_group 0;" ::: "memory");
        __syncthreads();

        const uint32_t bs = sb + (c & 1) * BUFSZ;
        #pragma unroll
        for (int ks = 0; ks < 4; ks++) {
            uint32_t af[2][4];
            #pragma unroll
            for (int mf = 0; mf < 2; mf++) {
                int row = wm * 32 + mf * 16 + a_rg;
                int u   = ks * 2 + a_u;
                ldmx4(af[mf], bs + OFF_A + (uint32_t)(row * 128 + ((u ^ (row & 7)) << 4)));
            }
            #pragma unroll
            for (int g = 0; g < 4; g++) {
                uint32_t bf[4];
                int row = wn * 64 + g * 16 + b_rg;
                int u   = ks * 2 + b_u;
                ldmx4(bf, bs + OFF_B + (uint32_t)(row * 128 + ((u ^ (row & 7)) << 4)));
                #pragma unroll
                for (int mf = 0; mf < 2; mf++) {
                    hmma(acc[mf][g * 2],     af[mf], bf[0], bf[1]);
                    hmma(acc[mf][g * 2 + 1], af[mf], bf[2], bf[3]);
                }
            }
        }
        __syncthreads();
        if (c + 2 < NCH) issue((c + 2) * 64, c & 1);
    }

    // -------- epilogue: tanh(E/64 + hb) . v
    float* hb_t = (float*)smem;                    // [256][33]
    float* v_s  = (float*)(smem + 33792);          // [256]
    float* red  = (float*)(smem + 34816);          // [128][4]
    for (int i = tid; i < 256 * BD; i += TPB) {
        int n = i >> 5, b = i & 31;
        hb_t[n * 33 + b] = g_hb[b * HD + n0 + n];
    }
    if (tid < 256) v_s[tid] = v[n0 + tid];
    __syncthreads();

    const float c1 = 1.0f / 64.0f;
    const int quad = lane >> 2, qlane = lane & 3;
    #pragma unroll
    for (int mf = 0; mf < 2; mf++) {
        #pragma unroll
        for (int h = 0; h < 2; h++) {
            int rl = wm * 32 + mf * 16 + h * 8 + quad;
            int b  = (m0 + rl) & 31;
            float p = 0.f;
            #pragma unroll
            for (int nf = 0; nf < 8; nf++) {
                int cl = wn * 64 + nf * 8 + qlane * 2;
                float e0 = fmaf(acc[mf][nf][h * 2],     c1, hb_t[cl * 33 + b]);
                float e1 = fmaf(acc[mf][nf][h * 2 + 1], c1, hb_t[(cl + 1) * 33 + b]);
                p = fmaf(tanh_fast(e0), v_s[cl],     p);
                p = fmaf(tanh_fast(e1), v_s[cl + 1], p);
            }
            p += __shfl_xor_sync(0xffffffffu, p, 1);
            p += __shfl_xor_sync(0xffffffffu, p, 2);
            if (qlane == 0) red[rl * 4 + wn] = p;
        }
    }
    __syncthreads();
    if (tid < 128) {
        int m = m0 + tid;
        float lg = red[tid * 4] + red[tid * 4 + 1] + red[tid * 4 + 2] + red[tid * 4 + 3];
        g_attnp[nsl * BD * SD + (m & 31) * SD + (m >> 5)] = lg;
    }
}

// ---------------- softmax over S per batch row (sums 2 N-slice partials)
__global__ void softmax_kernel(const int* __restrict__ mask, float* __restrict__ out) {
    int b = blockIdx.x;
    int tid = threadIdx.x;             // 256
    int warp = tid >> 5, lane = tid & 31;
    __shared__ float sred[8];

    float vals[8];
    float mx = -INFINITY;
    #pragma unroll
    for (int i = 0; i < 8; i++) {
        int s = tid + i * 256;
        float raw = g_attnp[b * SD + s] + g_attnp[BD * SD + b * SD + s];
        vals[i] = mask[b * SD + s] ? raw : NEGV;
        mx = fmaxf(mx, vals[i]);
    }
    #pragma unroll
    for (int o = 16; o > 0; o >>= 1) mx = fmaxf(mx, __shfl_xor_sync(0xffffffffu, mx, o));
    if (lane == 0) sred[warp] = mx;
    __syncthreads();
    float bm = sred[0];
    #pragma unroll
    for (int w = 1; w < 8; w++) bm = fmaxf(bm, sred[w]);

    float sum = 0.f;
    #pragma unroll
    for (int i = 0; i < 8; i++) {
        vals[i] = expf(vals[i] - bm);
        sum += vals[i];
    }
    #pragma unroll
    for (int o = 16; o > 0; o >>= 1) sum += __shfl_xor_sync(0xffffffffu, sum, o);
    __syncthreads();
    if (lane == 0) sred[warp] = sum;
    __syncthreads();
    float bs = 0.f;
    #pragma unroll
    for (int w = 0; w < 8; w++) bs += sred[w];
    float inv = 1.f / bs;
    #pragma unroll
    for (int i = 0; i < 8; i++) out[b * SD + tid + i * 256] = vals[i] * inv;
}

extern "C" void kernel_launch(void* const* d_in, const int* in_sizes, int n_in,
                              void* d_out, int out_size) {
    const float* hidden = (const float*)d_in[0];
    const float* eo     = (const float*)d_in[1];
    const int*   mask   = (const int*)  d_in[2];
    const float* attn_w = (const float*)d_in[3];
    const float* attn_b = (const float*)d_in[4];
    const float* v      = (const float*)d_in[5];
    float* out = (float*)d_out;

    cudaFuncSetAttribute(energy_kernel,
                         cudaFuncAttributeMaxDynamicSharedMemorySize, SMEM_TOTAL);

    prep_a_kernel<<<(SD * BD * K2) / (256 * 16), 256>>>(eo);
    prep_w_kernel<<<HD, 256>>>(attn_w);
    hb_kernel<<<dim3(8, BD), 256>>>(hidden, attn_w, attn_b);
    energy_kernel<<<dim3(SD * BD / 128, 2), TPB, SMEM_TOTAL>>>(v);
    softmax_kernel<<<BD, 256>>>(mask, out);
}

// round 8
// speedup vs baseline: 5.1344x; 1.0072x over previous
#include <cuda_runtime.h>
#include <cuda_fp16.h>
#include <math.h>
#include <stdint.h>

#define HD   512
#define BD   32
#define SD   2048
#define K2   1024
#define W4H  2048
#define NEGV (-1e10f)

#define TPB  512
#define NCH  16            /* k chunks of 64 */

#define OFF_A 0            /* 128 rows * 128B = 16KB */
#define OFF_B 16384        /* 256 rows * 128B = 32KB */
#define BUFSZ 49152
#define SMEM_TOTAL (2 * BUFSZ)

__device__ float g_hb[BD * HD];
__device__ float g_attnp[2 * BD * SD];
__device__ __align__(16) __half g_ah[(size_t)SD * BD * K2];
__device__ __align__(16) __half g_wh[HD * K2];

// ---------------------------------------------------------------- helpers
__device__ __forceinline__ uint32_t smem_u32(const void* p) {
    uint32_t a;
    asm("{ .reg .u64 t; cvta.to.shared.u64 t, %1; cvt.u32.u64 %0, t; }"
        : "=r"(a) : "l"(p));
    return a;
}
__device__ __forceinline__ void cp16(uint32_t dst, const void* src) {
    asm volatile("cp.async.cg.shared.global [%0], [%1], 16;"
                 :: "r"(dst), "l"(src) : "memory");
}
__device__ __forceinline__ void ldmx4(uint32_t* r, uint32_t addr) {
    asm volatile("ldmatrix.sync.aligned.m8n8.x4.shared.b16 {%0,%1,%2,%3}, [%4];"
                 : "=r"(r[0]), "=r"(r[1]), "=r"(r[2]), "=r"(r[3]) : "r"(addr));
}
__device__ __forceinline__ void hmma(float* c, const uint32_t* a,
                                     uint32_t b0, uint32_t b1) {
    asm("mma.sync.aligned.m16n8k16.row.col.f32.f16.f16.f32 "
        "{%0,%1,%2,%3}, {%4,%5,%6,%7}, {%8,%9}, {%0,%1,%2,%3};"
        : "+f"(c[0]), "+f"(c[1]), "+f"(c[2]), "+f"(c[3])
        : "r"(a[0]), "r"(a[1]), "r"(a[2]), "r"(a[3]), "r"(b0), "r"(b1));
}

// FMA-pipe-only tanh (no MUFU). |err| <= ~2.3e-5.
__device__ __forceinline__ float tanh_fast(float x) {
    float xa = fminf(fmaxf(x, -5.7f), 5.7f);
    float z  = xa * 2.885390081777927f;
    float fz = z + 12582912.0f;
    int   ni = __float_as_int(fz);
    float f  = z - (fz - 12582912.0f);
    float p  = 1.3333558146e-3f;
    p = fmaf(p, f, 9.6181291076e-3f);
    p = fmaf(p, f, 5.5504108664e-2f);
    p = fmaf(p, f, 2.4022650696e-1f);
    p = fmaf(p, f, 6.9314718056e-1f);
    p = fmaf(p, f, 1.0f);
    float s = __int_as_float((ni << 23) + 0x3F800000);
    float t = p * s;
    float d = t + 1.0f;
    float r = __int_as_float(0x7EF311C3 - __float_as_int(d));
    r = r * (2.0f - d * r);
    r = r * (2.0f - d * r);
    r = r * (2.0f - d * r);
    return (t - 1.0f) * r;
}

// ---------------- prep A: eo fp32 -> fp16
__global__ void prep_a_kernel(const float* __restrict__ eo) {
    size_t base = ((size_t)blockIdx.x * 256 + threadIdx.x) * 16;
    uint32_t o[8];
    #pragma unroll
    for (int i = 0; i < 4; i++) {
        float4 x = *(const float4*)(eo + base + i * 4);
        __half2 h01 = __floats2half2_rn(x.x, x.y);
        __half2 h23 = __floats2half2_rn(x.z, x.w);
        o[i * 2]     = *(uint32_t*)&h01;
        o[i * 2 + 1] = *(uint32_t*)&h23;
    }
    *(uint4*)(g_ah + base)     = make_uint4(o[0], o[1], o[2], o[3]);
    *(uint4*)(g_ah + base + 8) = make_uint4(o[4], o[5], o[6], o[7]);
}

// ---------------- prep W: attn_w[:,1024:2048] * 64 -> fp16
__global__ void prep_w_kernel(const float* __restrict__ attn_w) {
    int n = blockIdx.x;
    int k = threadIdx.x * 4;
    float4 w = *(const float4*)(attn_w + (size_t)n * W4H + 1024 + k);
    __half2 h01 = __floats2half2_rn(w.x * 64.f, w.y * 64.f);
    __half2 h23 = __floats2half2_rn(w.z * 64.f, w.w * 64.f);
    *(uint2*)(g_wh + (size_t)n * K2 + k) =
        make_uint2(*(uint32_t*)&h01, *(uint32_t*)&h23);
}

// ---------------- hb: g_hb[b][h] = bias[h] + hidden[b,:] . W[h, :1024]
__global__ void hb_kernel(const float* __restrict__ hidden,
                          const float* __restrict__ attn_w,
                          const float* __restrict__ attn_b) {
    int hc = blockIdx.x, b = blockIdx.y;
    __shared__ float sh[K2];
    for (int i = threadIdx.x; i < K2; i += 256) sh[i] = hidden[b * K2 + i];
    __syncthreads();
    int w = threadIdx.x >> 5, lane = threadIdx.x & 31;
    #pragma unroll
    for (int hi = 0; hi < 8; hi++) {
        int h = hc * 64 + w * 8 + hi;
        const float* wr = attn_w + (size_t)h * W4H;
        float s = 0.f;
        for (int k = lane * 4; k < K2; k += 128) {
            float4 wv = *(const float4*)(wr + k);
            s += sh[k] * wv.x + sh[k + 1] * wv.y + sh[k + 2] * wv.z + sh[k + 3] * wv.w;
        }
        #pragma unroll
        for (int o = 16; o > 0; o >>= 1) s += __shfl_down_sync(0xffffffffu, s, o);
        if (lane == 0) g_hb[b * HD + h] = s + attn_b[h];
    }
}

// ---------------- energy: fp16 HMMA GEMM, 16 warps, fragment-pipelined
__global__ void __launch_bounds__(TPB, 1)
energy_kernel(const float* __restrict__ v) {
    extern __shared__ char smem[];
    const uint32_t sb = smem_u32(smem);
    const int tid  = threadIdx.x;
    const int lane = tid & 31;
    const int warp = tid >> 5;
    const int wm   = warp >> 2;          // 0..3  (m32 quarter)
    const int wn   = warp & 3;           // 0..3  (n64 quarter)

    const int m0  = blockIdx.x * 128;
    const int nsl = blockIdx.y;
    const int n0  = nsl * 256;

    float acc[2][8][4];
    #pragma unroll
    for (int mf = 0; mf < 2; mf++)
        #pragma unroll
        for (int nf = 0; nf < 8; nf++)
            #pragma unroll
            for (int i = 0; i < 4; i++) acc[mf][nf][i] = 0.f;

    const int a_rg = (lane & 7) + ((lane >> 3) & 1) * 8;
    const int a_u  = lane >> 4;
    const int b_rg = (lane & 7) + ((lane >> 4) << 3);
    const int b_u  = (lane >> 3) & 1;

    auto issue = [&](int kc, int buf) {
        const uint32_t bs = sb + buf * BUFSZ;
        #pragma unroll
        for (int j = 0; j < 2; j++) {       // A: 128 rows x 8 units = 1024
            int x = tid + j * TPB;
            int r = x >> 3, u = x & 7;
            uint32_t d = (uint32_t)(r * 128 + ((u ^ (r & 7)) << 4));
            cp16(bs + OFF_A + d, g_ah + (size_t)(m0 + r) * K2 + kc + u * 8);
        }
        #pragma unroll
        for (int j = 0; j < 4; j++) {       // B: 256 rows x 8 units = 2048
            int x = tid + j * TPB;
            int r = x >> 3, u = x & 7;
            uint32_t d = (uint32_t)(r * 128 + ((u ^ (r & 7)) << 4));
            cp16(bs + OFF_B + d, g_wh + (size_t)(n0 + r) * K2 + kc + u * 8);
        }
        asm volatile("cp.async.commit_group;" ::: "memory");
    };

    // fragment address helpers
    auto a_addr = [&](uint32_t bs, int mf, int ks) -> uint32_t {
        int row = wm * 32 + mf * 16 + a_rg;
        int u   = ks * 2 + a_u;
        return bs + OFF_A + (uint32_t)(row * 128 + ((u ^ (row & 7)) << 4));
    };
    auto b_addr = [&](uint32_t bs, int g, int ks) -> uint32_t {
        int row = wn * 64 + g * 16 + b_rg;
        int u   = ks * 2 + b_u;
        return bs + OFF_B + (uint32_t)(row * 128 + ((u ^ (row & 7)) << 4));
    };

    issue(0, 0);
    issue(64, 1);

    for (int c = 0; c < NCH; c++) {
        if (c < NCH - 1) asm volatile("cp.async.wait_group 1;" ::: "memory");
        else             asm volatile("cp.async.wait_group 0;" ::: "memory");
        __syncthreads();

        const uint32_t bs = sb + (c & 1) * BUFSZ;

        uint32_t af_cur[2][4], af_nxt[2][4], bf_cur[4], bf_nxt[4];
        ldmx4(af_cur[0], a_addr(bs, 0, 0));
        ldmx4(af_cur[1], a_addr(bs, 1, 0));
        ldmx4(bf_cur, b_addr(bs, 0, 0));

        #pragma unroll
        for (int it = 0; it < 16; it++) {
            const int ks = it >> 2, g = it & 3;
            // prefetch next fragments before the dependent MMAs
            if (it < 15) {
                const int nks = (it + 1) >> 2, ng = (it + 1) & 3;
                ldmx4(bf_nxt, b_addr(bs, ng, nks));
                if (g == 3) {
                    ldmx4(af_nxt[0], a_addr(bs, 0, ks + 1));
                    ldmx4(af_nxt[1], a_addr(bs, 1, ks + 1));
                }
            }
            hmma(acc[0][g * 2],     af_cur[0], bf_cur[0], bf_cur[1]);
            hmma(acc[0][g * 2 + 1], af_cur[0], bf_cur[2], bf_cur[3]);
            hmma(acc[1][g * 2],     af_cur[1], bf_cur[0], bf_cur[1]);
            hmma(acc[1][g * 2 + 1], af_cur[1], bf_cur[2], bf_cur[3]);
            if (it < 15) {
                #pragma unroll
                for (int i = 0; i < 4; i++) bf_cur[i] = bf_nxt[i];
                if (g == 3) {
                    #pragma unroll
                    for (int i = 0; i < 4; i++) {
                        af_cur[0][i] = af_nxt[0][i];
                        af_cur[1][i] = af_nxt[1][i];
                    }
                }
            }
        }
        __syncthreads();
        if (c + 2 < NCH) issue((c + 2) * 64, c & 1);
    }

    // -------- epilogue: tanh(E/64 + hb) . v
    float* hb_t = (float*)smem;                    // [256][33]
    float* v_s  = (float*)(smem + 33792);          // [256]
    float* red  = (float*)(smem + 34816);          // [128][4]
    for (int i = tid; i < 256 * BD; i += TPB) {
        int n = i >> 5, b = i & 31;
        hb_t[n * 33 + b] = g_hb[b * HD + n0 + n];
    }
    if (tid < 256) v_s[tid] = v[n0 + tid];
    __syncthreads();

    const float c1 = 1.0f / 64.0f;
    const int quad = lane >> 2, qlane = lane & 3;
    #pragma unroll
    for (int mf = 0; mf < 2; mf++) {
        #pragma unroll
        for (int h = 0; h < 2; h++) {
            int rl = wm * 32 + mf * 16 + h * 8 + quad;
            int b  = (m0 + rl) & 31;
            float p = 0.f;
            #pragma unroll
            for (int nf = 0; nf < 8; nf++) {
                int cl = wn * 64 + nf * 8 + qlane * 2;
                float e0 = fmaf(acc[mf][nf][h * 2],     c1, hb_t[cl * 33 + b]);
                float e1 = fmaf(acc[mf][nf][h * 2 + 1], c1, hb_t[(cl + 1) * 33 + b]);
                p = fmaf(tanh_fast(e0), v_s[cl],     p);
                p = fmaf(tanh_fast(e1), v_s[cl + 1], p);
            }
            p += __shfl_xor_sync(0xffffffffu, p, 1);
            p += __shfl_xor_sync(0xffffffffu, p, 2);
            if (qlane == 0) red[rl * 4 + wn] = p;
        }
    }
    __syncthreads();
    if (tid < 128) {
        int m = m0 + tid;
        float lg = red[tid * 4] + red[tid * 4 + 1] + red[tid * 4 + 2] + red[tid * 4 + 3];
        g_attnp[nsl * BD * SD + (m & 31) * SD + (m >> 5)] = lg;
    }
}

// ---------------- softmax over S per batch row (sums 2 N-slice partials)
__global__ void softmax_kernel(const int* __restrict__ mask, float* __restrict__ out) {
    int b = blockIdx.x;
    int tid = threadIdx.x;             // 256
    int warp = tid >> 5, lane = tid & 31;
    __shared__ float sred[8];

    float vals[8];
    float mx = -INFINITY;
    #pragma unroll
    for (int i = 0; i < 8; i++) {
        int s = tid + i * 256;
        float raw = g_attnp[b * SD + s] + g_attnp[BD * SD + b * SD + s];
        vals[i] = mask[b * SD + s] ? raw : NEGV;
        mx = fmaxf(mx, vals[i]);
    }
    #pragma unroll
    for (int o = 16; o > 0; o >>= 1) mx = fmaxf(mx, __shfl_xor_sync(0xffffffffu, mx, o));
    if (lane == 0) sred[warp] = mx;
    __syncthreads();
    float bm = sred[0];
    #pragma unroll
    for (int w = 1; w < 8; w++) bm = fmaxf(bm, sred[w]);

    float sum = 0.f;
    #pragma unroll
    for (int i = 0; i < 8; i++) {
        vals[i] = expf(vals[i] - bm);
        sum += vals[i];
    }
    #pragma unroll
    for (int o = 16; o > 0; o >>= 1) sum += __shfl_xor_sync(0xffffffffu, sum, o);
    __syncthreads();
    if (lane == 0) sred[warp] = sum;
    __syncthreads();
    float bs = 0.f;
    #pragma unroll
    for (int w = 0; w < 8; w++) bs += sred[w];
    float inv = 1.f / bs;
    #pragma unroll
    for (int i = 0; i < 8; i++) out[b * SD + tid + i * 256] = vals[i] * inv;
}

extern "C" void kernel_launch(void* const* d_in, const int* in_sizes, int n_in,
                              void* d_out, int out_size) {
    const float* hidden = (const float*)d_in[0];
    const float* eo     = (const float*)d_in[1];
    const int*   mask   = (const int*)  d_in[2];
    const float* attn_w = (const float*)d_in[3];
    const float* attn_b = (const float*)d_in[4];
    const float* v      = (const float*)d_in[5];
    float* out = (float*)d_out;

    cudaFuncSetAttribute(energy_kernel,
                         cudaFuncAttributeMaxDynamicSharedMemorySize, SMEM_TOTAL);

    prep_a_kernel<<<(SD * BD * K2) / (256 * 16), 256>>>(eo);
    prep_w_kernel<<<HD, 256>>>(attn_w);
    hb_kernel<<<dim3(8, BD), 256>>>(hidden, attn_w, attn_b);
    energy_kernel<<<dim3(SD * BD / 128, 2), TPB, SMEM_TOTAL>>>(v);
    softmax_kernel<<<BD, 256>>>(mask, out);
}